// round 15
// baseline (speedup 1.0000x reference)
#include <cuda_runtime.h>
#include <cuda_bf16.h>
#include <cuda_fp16.h>
#include <cstdint>

#define NN 500000
#define NE 1250000
#define HID 64
#define NG 512
#define NC 10

#define SCAN_T 256
#define SCAN_I 4
#define SCAN_B (SCAN_T*SCAN_I)   // 1024

// ---------------- device scratch ----------------
__device__ int      g_idx64;
__device__ int      d_degE[NN];
__device__ float    d_dinv[NN];
__device__ int      d_rowptr[NN];
__device__ int      d_cursor[NN];
__device__ int      d_bsums[512];
__device__ float4   d_metaf[NN];     // {rowptr, deg, dinv, -}
__device__ int4     d_elli[NN];      // first 4 edge indices (self-padded)
__device__ float4   d_ellw[NN];      // first 4 edge weights (self slot = dinv when deg<4)
__device__ float2   d_colw[NE];      // CSR tail (slots >= 4 only)
__device__ __half   d_hbuf[(size_t)NN*HID];
__device__ __half   d_tbuf[(size_t)NN*HID];
__device__ float    d_gsum[NG*HID];
__device__ unsigned d_gmax[NG*HID];
__device__ int      d_cnt[NG];
// probe sinks (never read; keep probe side-effect-free w.r.t. output)
__device__ float    d_gsumS[NG*HID];
__device__ unsigned d_gmaxS[NG*HID];
__device__ int      d_cntS[NG];

__device__ __forceinline__ int ld_idx32(const void* p, long long j, int is64) {
    const unsigned* u = (const unsigned*)p;
    return (int)(is64 ? u[2*j] : u[j]);
}

// ---------------- index-width detection ----------------
__global__ void detect_kernel(const unsigned* __restrict__ p) {
    __shared__ unsigned red[256];
    int t = threadIdx.x;
    unsigned v = 0;
    for (int i = 2 * t + 1; i < 4096; i += 512) v |= p[i];
    red[t] = v;
    __syncthreads();
    for (int off = 128; off > 0; off >>= 1) {
        if (t < off) red[t] |= red[t + off];
        __syncthreads();
    }
    if (t == 0) g_idx64 = (red[0] == 0) ? 1 : 0;
}

__global__ void zero_kernel(int n) {
    int i = blockIdx.x * blockDim.x + threadIdx.x;
    if (i < n) d_degE[i] = 0;
    if (i < NG * HID) { d_gsum[i] = 0.f; d_gmax[i] = 0u; }
    if (i < NG) d_cnt[i] = 0;
}

__global__ void hist_kernel(const void* __restrict__ ei, int E) {
    int e = blockIdx.x * blockDim.x + threadIdx.x;
    if (e >= E) return;
    int dd = ld_idx32(ei, (long long)E + e, g_idx64);
    atomicAdd(&d_degE[dd], 1);
}

__global__ void dinv_kernel(int n) {
    int i = blockIdx.x * blockDim.x + threadIdx.x;
    if (i < n) d_dinv[i] = rsqrtf((float)d_degE[i] + 1.0f);
}

// ---------------- exclusive scan ----------------
__global__ void scanA_kernel(int n) {
    __shared__ int sm[SCAN_T];
    int b = blockIdx.x, t = threadIdx.x;
    int base = b * SCAN_B + t * SCAN_I;
    int v[SCAN_I];
    int s = 0;
#pragma unroll
    for (int j = 0; j < SCAN_I; j++) {
        v[j] = (base + j < n) ? d_degE[base + j] : 0;
        s += v[j];
    }
    sm[t] = s;
    __syncthreads();
    for (int off = 1; off < SCAN_T; off <<= 1) {
        int x = (t >= off) ? sm[t - off] : 0;
        __syncthreads();
        sm[t] += x;
        __syncthreads();
    }
    int excl = (t > 0) ? sm[t - 1] : 0;
    if (t == SCAN_T - 1) d_bsums[b] = sm[t];
    int run = excl;
#pragma unroll
    for (int j = 0; j < SCAN_I; j++) {
        if (base + j < n) d_rowptr[base + j] = run;
        run += v[j];
    }
}

__global__ void scanB_kernel(int nb) {
    __shared__ int sm[512];
    int t = threadIdx.x;
    sm[t] = (t < nb) ? d_bsums[t] : 0;
    __syncthreads();
    for (int off = 1; off < 512; off <<= 1) {
        int x = (t >= off) ? sm[t - off] : 0;
        __syncthreads();
        sm[t] += x;
        __syncthreads();
    }
    int excl = (t > 0) ? sm[t - 1] : 0;
    if (t < nb) d_bsums[t] = excl;
}

__global__ void scanC_kernel(int n) {
    int i = blockIdx.x * blockDim.x + threadIdx.x;
    if (i < n) {
        int v = d_rowptr[i] + d_bsums[i / SCAN_B];
        d_rowptr[i] = v;
        d_cursor[i] = v;
        int cnt = d_degE[i];
        float di = d_dinv[i];
        d_metaf[i] = make_float4(__int_as_float(v), __int_as_float(cnt), di, 0.f);
        d_elli[i] = make_int4(i, i, i, i);
        d_ellw[i] = make_float4(cnt == 0 ? di : 0.f, cnt == 1 ? di : 0.f,
                                cnt == 2 ? di : 0.f, cnt == 3 ? di : 0.f);
    }
}

__global__ void scatter_kernel(const void* __restrict__ ei, int E) {
    int e = blockIdx.x * blockDim.x + threadIdx.x;
    if (e >= E) return;
    int is64 = g_idx64;
    int ss = ld_idx32(ei, e, is64);
    int dd = ld_idx32(ei, (long long)E + e, is64);
    int pos = atomicAdd(&d_cursor[dd], 1);
    int j = pos - d_rowptr[dd];
    float wv = d_dinv[ss];
    if (j < 4) {
        ((int*)&d_elli[dd])[j] = ss;
        ((float*)&d_ellw[dd])[j] = wv;
    } else {
        d_colw[pos] = make_float2(__int_as_float(ss), wv);
    }
}

// ---------------- fast bf16x2 split (layer-0 GEMM) ----------------
__device__ __forceinline__ void split2(float v0, float v1, uint32_t& hi, uint32_t& lo) {
    uint32_t h;
    asm("cvt.rn.bf16x2.f32 %0, %1, %2;" : "=r"(h) : "f"(v1), "f"(v0));
    float f0 = __uint_as_float(h << 16);
    float f1 = __uint_as_float(h & 0xFFFF0000u);
    asm("cvt.rn.bf16x2.f32 %0, %1, %2;" : "=r"(lo) : "f"(v1 - f1), "f"(v0 - f0));
    hi = h;
}

// ---------------- f16x2 split (W for fused layers) ----------------
__device__ __forceinline__ void split2h(float v0, float v1, uint32_t& hi, uint32_t& lo) {
    __half2 h2 = __floats2half2_rn(v0, v1);
    float2 f = __half22float2(h2);
    __half2 l2 = __floats2half2_rn(v0 - f.x, v1 - f.y);
    hi = *(uint32_t*)&h2;
    lo = *(uint32_t*)&l2;
}

#define MMA_BF16(c, a, b0v, b1v) \
    asm volatile("mma.sync.aligned.m16n8k16.row.col.f32.bf16.bf16.f32 " \
        "{%0,%1,%2,%3}, {%4,%5,%6,%7}, {%8,%9}, {%0,%1,%2,%3};" \
        : "+f"((c)[0]), "+f"((c)[1]), "+f"((c)[2]), "+f"((c)[3]) \
        : "r"((a)[0]), "r"((a)[1]), "r"((a)[2]), "r"((a)[3]), "r"(b0v), "r"(b1v))

#define MMA_F16(c, a, b0v, b1v) \
    asm volatile("mma.sync.aligned.m16n8k16.row.col.f32.f16.f16.f32 " \
        "{%0,%1,%2,%3}, {%4,%5,%6,%7}, {%8,%9}, {%0,%1,%2,%3};" \
        : "+f"((c)[0]), "+f"((c)[1]), "+f"((c)[2]), "+f"((c)[3]) \
        : "r"((a)[0]), "r"((a)[1]), "r"((a)[2]), "r"((a)[3]), "r"(b0v), "r"(b1v))

// ---------------- layer-0 GEMM: t[N,64] = in[N,128] @ W[128,64], fp16 output ----------------
__global__ void __launch_bounds__(256, 2) gemm_mma128(const float* __restrict__ in,
                                                      const float* __restrict__ W,
                                                      __half* __restrict__ out, int n) {
    constexpr int K = 128, K2 = 64, WST = 72, NKC = 8;
    __shared__ uint32_t Wh[K2 * WST];
    __shared__ uint32_t Wl[K2 * WST];

    int tid = threadIdx.x, wid = tid >> 5, lane = tid & 31;
    int rb = blockIdx.x * 128;
    int nrows = min(128, n - rb);

    for (int i = tid; i < K2 * 64; i += 256) {
        int p = i >> 6, nn = i & 63;
        int chunk = p >> 3, m = p & 7;
        int o = (chunk << 3) + ((m < 4) ? 2 * m : 2 * (m - 4) + 1);
        uint32_t hi, lo;
        split2(W[(2 * o) * 64 + nn], W[(2 * o + 1) * 64 + nn], hi, lo);
        Wh[p * WST + nn] = hi;
        Wl[p * WST + nn] = lo;
    }
    __syncthreads();

    int qr = lane >> 2, qc = lane & 3;
    int r0 = wid * 16 + qr;
    const float* base0 = in + (size_t)(rb + min(r0, nrows - 1)) * K;
    const float* base1 = in + (size_t)(rb + min(r0 + 8, nrows - 1)) * K;

    float acc[8][4];
#pragma unroll
    for (int t = 0; t < 8; t++)
#pragma unroll
        for (int j = 0; j < 4; j++) acc[t][j] = 0.f;

    float4 pf[2][2];
    pf[0][0] = __ldg((const float4*)(base0 + 4 * qc));
    pf[0][1] = __ldg((const float4*)(base1 + 4 * qc));
    pf[1][0] = __ldg((const float4*)(base0 + 16 + 4 * qc));
    pf[1][1] = __ldg((const float4*)(base1 + 16 + 4 * qc));

#pragma unroll
    for (int kc = 0; kc < NKC; kc++) {
        float4 a0 = pf[kc & 1][0], a1 = pf[kc & 1][1];
        if (kc + 2 < NKC) {
            int cn = (kc + 2) * 16 + 4 * qc;
            pf[kc & 1][0] = __ldg((const float4*)(base0 + cn));
            pf[kc & 1][1] = __ldg((const float4*)(base1 + cn));
        }
        uint32_t ah[4], al[4];
        split2(a0.x, a0.y, ah[0], al[0]);
        split2(a1.x, a1.y, ah[1], al[1]);
        split2(a0.z, a0.w, ah[2], al[2]);
        split2(a1.z, a1.w, ah[3], al[3]);

        int bb = (kc * 8 + qc) * WST + qr;
#pragma unroll
        for (int t = 0; t < 8; t++) {
            uint32_t bh0 = Wh[bb + 8 * t];
            uint32_t bh1 = Wh[bb + 4 * WST + 8 * t];
            uint32_t bl0 = Wl[bb + 8 * t];
            uint32_t bl1 = Wl[bb + 4 * WST + 8 * t];
            MMA_BF16(acc[t], ah, bh0, bh1);
            MMA_BF16(acc[t], ah, bl0, bl1);
            MMA_BF16(acc[t], al, bh0, bh1);
        }
    }

    bool ok0 = (r0 < nrows), ok1 = (r0 + 8 < nrows);
    __half* o0 = out + (size_t)(rb + r0) * 64;
    __half* o1 = out + (size_t)(rb + r0 + 8) * 64;
#pragma unroll
    for (int t = 0; t < 8; t++) {
        int c = 8 * t + qc * 2;
        if (ok0) *(__half2*)(o0 + c) = __floats2half2_rn(acc[t][0], acc[t][1]);
        if (ok1) *(__half2*)(o1 + c) = __floats2half2_rn(acc[t][2], acc[t][3]);
    }
}

// ---------------- ELL aggregate body: 4 preloaded gathers + self/tail for deg>=4 ----------------
__device__ __forceinline__ float4 agg_body_ell(const uint2* __restrict__ t2, int c4,
                                               float di, const uint2* u, float4 ew,
                                               int start, int cnt, int selfi, float4 bb) {
    float ax = 0.f, ay = 0.f, az = 0.f, aw = 0.f;
    float2 a, b;
    a = __half22float2(*(const __half2*)&u[0].x); b = __half22float2(*(const __half2*)&u[0].y);
    ax += ew.x * a.x; ay += ew.x * a.y; az += ew.x * b.x; aw += ew.x * b.y;
    a = __half22float2(*(const __half2*)&u[1].x); b = __half22float2(*(const __half2*)&u[1].y);
    ax += ew.y * a.x; ay += ew.y * a.y; az += ew.y * b.x; aw += ew.y * b.y;
    a = __half22float2(*(const __half2*)&u[2].x); b = __half22float2(*(const __half2*)&u[2].y);
    ax += ew.z * a.x; ay += ew.z * a.y; az += ew.z * b.x; aw += ew.z * b.y;
    a = __half22float2(*(const __half2*)&u[3].x); b = __half22float2(*(const __half2*)&u[3].y);
    ax += ew.w * a.x; ay += ew.w * a.y; az += ew.w * b.x; aw += ew.w * b.y;
    if (cnt >= 4) {
        uint2 sv = __ldg(t2 + (size_t)selfi * 16 + c4);
        a = __half22float2(*(const __half2*)&sv.x); b = __half22float2(*(const __half2*)&sv.y);
        ax += di * a.x; ay += di * a.y; az += di * b.x; aw += di * b.y;
        for (int j = 4; j < cnt; j += 4) {
            int lim = cnt - 1;
            float2 c0 = __ldg(&d_colw[start + j]);
            float2 c1 = __ldg(&d_colw[start + min(j + 1, lim)]);
            float2 c2 = __ldg(&d_colw[start + min(j + 2, lim)]);
            float2 c3 = __ldg(&d_colw[start + min(j + 3, lim)]);
            float w0 = c0.y;
            float w1 = (j + 1 <= lim) ? c1.y : 0.f;
            float w2 = (j + 2 <= lim) ? c2.y : 0.f;
            float w3 = (j + 3 <= lim) ? c3.y : 0.f;
            uint2 v0 = __ldg(t2 + (size_t)__float_as_int(c0.x) * 16 + c4);
            uint2 v1 = __ldg(t2 + (size_t)__float_as_int(c1.x) * 16 + c4);
            uint2 v2 = __ldg(t2 + (size_t)__float_as_int(c2.x) * 16 + c4);
            uint2 v3 = __ldg(t2 + (size_t)__float_as_int(c3.x) * 16 + c4);
            a = __half22float2(*(const __half2*)&v0.x); b = __half22float2(*(const __half2*)&v0.y);
            ax += w0 * a.x; ay += w0 * a.y; az += w0 * b.x; aw += w0 * b.y;
            a = __half22float2(*(const __half2*)&v1.x); b = __half22float2(*(const __half2*)&v1.y);
            ax += w1 * a.x; ay += w1 * a.y; az += w1 * b.x; aw += w1 * b.y;
            a = __half22float2(*(const __half2*)&v2.x); b = __half22float2(*(const __half2*)&v2.y);
            ax += w2 * a.x; ay += w2 * a.y; az += w2 * b.x; aw += w2 * b.y;
            a = __half22float2(*(const __half2*)&v3.x); b = __half22float2(*(const __half2*)&v3.y);
            ax += w3 * a.x; ay += w3 * a.y; az += w3 * b.x; aw += w3 * b.y;
        }
    }
    return make_float4(fmaxf(di * ax + bb.x, 0.f), fmaxf(di * ay + bb.y, 0.f),
                       fmaxf(di * az + bb.z, 0.f), fmaxf(di * aw + bb.w, 0.f));
}

// ---------------- fused aggregate + GEMM64 (f16 A, f16 hi/lo W, 2-pass MMA) ----------------
__global__ void __launch_bounds__(256, 4) fused_agg_gemm(const __half* __restrict__ t,
                                                         const float* __restrict__ bias,
                                                         const float* __restrict__ W,
                                                         __half* __restrict__ out, int n) {
    constexpr int AST = 36, WST = 72, NKC = 4;
    extern __shared__ uint32_t sm[];
    uint32_t* Ast = sm;                  // [128][36] f16x2 words
    uint32_t* Wh = Ast + 128 * AST;      // [32][72]
    uint32_t* Wl = Wh + 32 * WST;

    int tid = threadIdx.x, wid = tid >> 5, lane = tid & 31;
    int rb = blockIdx.x * 128;
    int nrows = min(128, n - rb);

    for (int i = tid; i < 32 * 64; i += 256) {
        int k2 = i >> 6, nn = i & 63;
        uint32_t hi, lo;
        split2h(W[(2 * k2) * 64 + nn], W[(2 * k2 + 1) * 64 + nn], hi, lo);
        Wh[k2 * WST + nn] = hi;
        Wl[k2 * WST + nn] = lo;
    }

    // phase 1: half-warp per node, groups 2-ahead, gathers 1-ahead
    {
        int half = lane >> 4, c4 = lane & 15;
        const uint2* t2 = (const uint2*)t;
        float4 bb = __ldg((const float4*)bias + c4);
        int base = wid * 16 + half * 8;
        int ilim = nrows - 1;

        int iA = rb + min(base, ilim);
        float4 mA = __ldg(&d_metaf[iA]);
        int4   eA = __ldg(&d_elli[iA]);
        float4 wA = __ldg(&d_ellw[iA]);
        int iB = rb + min(base + 1, ilim);
        float4 mB = __ldg(&d_metaf[iB]);
        int4   eB = __ldg(&d_elli[iB]);
        float4 wB = __ldg(&d_ellw[iB]);
        uint2 u0 = __ldg(t2 + (size_t)eA.x * 16 + c4);
        uint2 u1 = __ldg(t2 + (size_t)eA.y * 16 + c4);
        uint2 u2 = __ldg(t2 + (size_t)eA.z * 16 + c4);
        uint2 u3 = __ldg(t2 + (size_t)eA.w * 16 + c4);

#pragma unroll 1
        for (int p = 0; p < 8; p++) {
            float4 mC = mB; int4 eC = eB; float4 wC = wB;
            if (p + 2 < 8) {
                int iC = rb + min(base + p + 2, ilim);
                mC = __ldg(&d_metaf[iC]);
                eC = __ldg(&d_elli[iC]);
                wC = __ldg(&d_ellw[iC]);
            }
            uint2 n0 = u0, n1 = u1, n2 = u2, n3 = u3;
            if (p + 1 < 8) {
                n0 = __ldg(t2 + (size_t)eB.x * 16 + c4);
                n1 = __ldg(t2 + (size_t)eB.y * 16 + c4);
                n2 = __ldg(t2 + (size_t)eB.z * 16 + c4);
                n3 = __ldg(t2 + (size_t)eB.w * 16 + c4);
            }
            int r = base + p;
            uint2 uu[4] = {u0, u1, u2, u3};
            float4 h = make_float4(0.f, 0.f, 0.f, 0.f);
            if (r < nrows)
                h = agg_body_ell(t2, c4, mA.z, uu, wA,
                                 __float_as_int(mA.x), __float_as_int(mA.y), rb + r, bb);
            __half2 p0 = __floats2half2_rn(h.x, h.y);
            __half2 p1 = __floats2half2_rn(h.z, h.w);
            Ast[r * AST + 2 * c4] = *(uint32_t*)&p0;
            Ast[r * AST + 2 * c4 + 1] = *(uint32_t*)&p1;
            mA = mB; eA = eB; wA = wB;
            mB = mC; eB = eC; wB = wC;
            u0 = n0; u1 = n1; u2 = n2; u3 = n3;
        }
    }
    __syncthreads();

    // phase 2: f16 MMA from smem, 2 passes (Whi, Wlo)
    int qr = lane >> 2, qc = lane & 3;
    int r0 = wid * 16 + qr;
    float acc[8][4];
#pragma unroll
    for (int t8 = 0; t8 < 8; t8++)
#pragma unroll
        for (int j = 0; j < 4; j++) acc[t8][j] = 0.f;

#pragma unroll
    for (int kc = 0; kc < NKC; kc++) {
        int ab = r0 * AST + kc * 8 + qc;
        uint32_t a4[4];
        a4[0] = Ast[ab];         a4[1] = Ast[ab + 8 * AST];
        a4[2] = Ast[ab + 4];     a4[3] = Ast[ab + 8 * AST + 4];
        int bb2 = (kc * 8 + qc) * WST + qr;
#pragma unroll
        for (int t8 = 0; t8 < 8; t8++) {
            uint32_t bh0 = Wh[bb2 + 8 * t8];
            uint32_t bh1 = Wh[bb2 + 4 * WST + 8 * t8];
            uint32_t bl0 = Wl[bb2 + 8 * t8];
            uint32_t bl1 = Wl[bb2 + 4 * WST + 8 * t8];
            MMA_F16(acc[t8], a4, bh0, bh1);
            MMA_F16(acc[t8], a4, bl0, bl1);
        }
    }

    bool ok0 = (r0 < nrows), ok1 = (r0 + 8 < nrows);
    __half* o0 = out + (size_t)(rb + r0) * 64;
    __half* o1 = out + (size_t)(rb + r0 + 8) * 64;
#pragma unroll
    for (int t8 = 0; t8 < 8; t8++) {
        int c = 8 * t8 + qc * 2;
        if (ok0) *(__half2*)(o0 + c) = __floats2half2_rn(acc[t8][0], acc[t8][1]);
        if (ok1) *(__half2*)(o1 + c) = __floats2half2_rn(acc[t8][2], acc[t8][3]);
    }
}

// ---------------- fused aggregate + pool (ELL, deep pipeline; parameterized sinks) ----------------
__global__ void __launch_bounds__(256, 4) fused_agg_pool(const __half* __restrict__ t,
                                                         const float* __restrict__ bias,
                                                         const void* __restrict__ batch,
                                                         float* __restrict__ gs,
                                                         unsigned* __restrict__ gm,
                                                         int* __restrict__ gc, int n) {
    int tid = threadIdx.x, wid = tid >> 5, lane = tid & 31;
    int half = lane >> 4, c4 = lane & 15;
    int is64 = g_idx64;
    const uint2* t2 = (const uint2*)t;
    float4 bb = __ldg((const float4*)bias + c4);
    int base = blockIdx.x * 128 + wid * 16 + half * 8;
    if (base >= n) return;
    int ilim = n - 1;

    int curg = -1, lc = 0;
    float4 ls = make_float4(0.f, 0.f, 0.f, 0.f);
    float4 lm = make_float4(0.f, 0.f, 0.f, 0.f);

    auto flush = [&]() {
        if (curg >= 0) {
            int o = curg * HID + 4 * c4;
            atomicAdd(&gs[o + 0], ls.x);
            atomicAdd(&gs[o + 1], ls.y);
            atomicAdd(&gs[o + 2], ls.z);
            atomicAdd(&gs[o + 3], ls.w);
            atomicMax(&gm[o + 0], __float_as_uint(lm.x));
            atomicMax(&gm[o + 1], __float_as_uint(lm.y));
            atomicMax(&gm[o + 2], __float_as_uint(lm.z));
            atomicMax(&gm[o + 3], __float_as_uint(lm.w));
            if (c4 == 0) atomicAdd(&gc[curg], lc);
        }
    };

    int iA = min(base, ilim);
    float4 mA = __ldg(&d_metaf[iA]);
    int4   eA = __ldg(&d_elli[iA]);
    float4 wA = __ldg(&d_ellw[iA]);
    int iB = min(base + 1, ilim);
    float4 mB = __ldg(&d_metaf[iB]);
    int4   eB = __ldg(&d_elli[iB]);
    float4 wB = __ldg(&d_ellw[iB]);
    uint2 u0 = __ldg(t2 + (size_t)eA.x * 16 + c4);
    uint2 u1 = __ldg(t2 + (size_t)eA.y * 16 + c4);
    uint2 u2 = __ldg(t2 + (size_t)eA.z * 16 + c4);
    uint2 u3 = __ldg(t2 + (size_t)eA.w * 16 + c4);

#pragma unroll 1
    for (int p = 0; p < 8; p++) {
        float4 mC = mB; int4 eC = eB; float4 wC = wB;
        if (p + 2 < 8) {
            int iC = min(base + p + 2, ilim);
            mC = __ldg(&d_metaf[iC]);
            eC = __ldg(&d_elli[iC]);
            wC = __ldg(&d_ellw[iC]);
        }
        uint2 n0 = u0, n1 = u1, n2 = u2, n3 = u3;
        if (p + 1 < 8) {
            n0 = __ldg(t2 + (size_t)eB.x * 16 + c4);
            n1 = __ldg(t2 + (size_t)eB.y * 16 + c4);
            n2 = __ldg(t2 + (size_t)eB.z * 16 + c4);
            n3 = __ldg(t2 + (size_t)eB.w * 16 + c4);
        }
        int i = base + p;
        if (i < n) {
            int g = ld_idx32(batch, i, is64);
            if (g != curg) {
                flush();
                curg = g; lc = 0;
                ls = make_float4(0.f, 0.f, 0.f, 0.f);
                lm = make_float4(0.f, 0.f, 0.f, 0.f);
            }
            uint2 uu[4] = {u0, u1, u2, u3};
            float4 h = agg_body_ell(t2, c4, mA.z, uu, wA,
                                    __float_as_int(mA.x), __float_as_int(mA.y), i, bb);
            ls.x += h.x; ls.y += h.y; ls.z += h.z; ls.w += h.w;
            lm.x = fmaxf(lm.x, h.x); lm.y = fmaxf(lm.y, h.y);
            lm.z = fmaxf(lm.z, h.z); lm.w = fmaxf(lm.w, h.w);
            lc++;
        }
        mA = mB; eA = eB; wA = wB;
        mB = mC; eB = eC; wB = wC;
        u0 = n0; u1 = n1; u2 = n2; u3 = n3;
    }
    flush();
}

// ---------------- final ----------------
__global__ void final_kernel(const float* __restrict__ Wout, const float* __restrict__ bout,
                             float* __restrict__ out) {
    __shared__ float p[2 * HID];
    int g = blockIdx.x;
    int t = threadIdx.x;  // 128
    if (t < HID) {
        float cn = fmaxf((float)d_cnt[g], 1.f);
        p[t] = d_gsum[g * HID + t] / cn;
        p[HID + t] = __uint_as_float(d_gmax[g * HID + t]);
    }
    __syncthreads();
    if (t < NC) {
        float a = bout[t];
#pragma unroll 16
        for (int k = 0; k < 2 * HID; k++) a += p[k] * Wout[k * NC + t];
        out[g * NC + t] = a;
    }
}

// ---------------- launch ----------------
extern "C" void kernel_launch(void* const* d_in, const int* in_sizes, int n_in,
                              void* d_out, int out_size) {
    const float* x    = (const float*)d_in[0];
    const void*  ei   = d_in[1];
    const void*  bat  = d_in[2];
    const float* W0   = (const float*)d_in[3];
    const float* b0   = (const float*)d_in[4];
    const float* W1   = (const float*)d_in[5];
    const float* b1   = (const float*)d_in[6];
    const float* W2   = (const float*)d_in[7];
    const float* b2   = (const float*)d_in[8];
    const float* Wout = (const float*)d_in[9];
    const float* bout = (const float*)d_in[10];
    float* out = (float*)d_out;

    int N = in_sizes[2];
    int E = in_sizes[1] / 2;

    __half *hp, *tp;
    cudaGetSymbolAddress((void**)&hp, d_hbuf);
    cudaGetSymbolAddress((void**)&tp, d_tbuf);
    float *gsp; unsigned *gmp; int *gcp;
    cudaGetSymbolAddress((void**)&gsp, d_gsum);
    cudaGetSymbolAddress((void**)&gmp, d_gmax);
    cudaGetSymbolAddress((void**)&gcp, d_cnt);
    float *gspS; unsigned *gmpS; int *gcpS;
    cudaGetSymbolAddress((void**)&gspS, d_gsumS);
    cudaGetSymbolAddress((void**)&gmpS, d_gmaxS);
    cudaGetSymbolAddress((void**)&gcpS, d_cntS);

    int fsmem = (128 * 36 + 2 * 32 * 72) * 4;  // 36864
    cudaFuncSetAttribute(fused_agg_gemm, cudaFuncAttributeMaxDynamicSharedMemorySize, fsmem);

    int gblk = (N + 127) / 128;

    static cudaStream_t s2 = nullptr;
    static cudaEvent_t evFork = nullptr, evJoin = nullptr;
    if (s2 == nullptr) {
        cudaStreamCreateWithFlags(&s2, cudaStreamNonBlocking);
        cudaEventCreateWithFlags(&evFork, cudaEventDisableTiming);
        cudaEventCreateWithFlags(&evJoin, cudaEventDisableTiming);
    }

    // fork: CSR build on s2, layer-0 GEMM on main stream
    cudaEventRecord(evFork, 0);
    cudaStreamWaitEvent(s2, evFork, 0);

    detect_kernel<<<1, 256, 0, s2>>>((const unsigned*)ei);
    zero_kernel<<<(N + 255) / 256, 256, 0, s2>>>(N);
    hist_kernel<<<(E + 255) / 256, 256, 0, s2>>>(ei, E);
    // PROFILING PROBE (4th code-order launch -> ncu capture slot): pool kernel on
    // replay-stable inputs, writing to sink buffers that nothing ever reads.
    fused_agg_pool<<<256, 256, 0, s2>>>(tp, b2, bat, gspS, gmpS, gcpS, N);
    dinv_kernel<<<(N + 255) / 256, 256, 0, s2>>>(N);
    int nb = (N + SCAN_B - 1) / SCAN_B;
    scanA_kernel<<<nb, SCAN_T, 0, s2>>>(N);
    scanB_kernel<<<1, 512, 0, s2>>>(nb);
    scanC_kernel<<<(N + 255) / 256, 256, 0, s2>>>(N);
    scatter_kernel<<<(E + 255) / 256, 256, 0, s2>>>(ei, E);

    gemm_mma128<<<gblk, 256>>>(x, W0, tp, N);

    cudaEventRecord(evJoin, s2);
    cudaStreamWaitEvent(0, evJoin, 0);

    fused_agg_gemm<<<gblk, 256, fsmem>>>(tp, b0, W1, hp, N);
    fused_agg_gemm<<<gblk, 256, fsmem>>>(hp, b1, W2, tp, N);
    fused_agg_pool<<<gblk, 256>>>(tp, b2, bat, gsp, gmp, gcp, N);
    final_kernel<<<NG, 128>>>(Wout, bout, out);
}

// round 16
// speedup vs baseline: 1.0562x; 1.0562x over previous
#include <cuda_runtime.h>
#include <cuda_bf16.h>
#include <cuda_fp16.h>
#include <cstdint>

#define NN 500000
#define NE 1250000
#define HID 64
#define NG 512
#define NC 10

#define SCAN_T 256
#define SCAN_I 4
#define SCAN_B (SCAN_T*SCAN_I)   // 1024

// ---------------- device scratch ----------------
__device__ int      g_idx64;
__device__ int      d_degE[NN];
__device__ float    d_dinv[NN];
__device__ int      d_rowptr[NN];
__device__ int      d_cursor[NN];
__device__ int      d_bsums[512];
__device__ float4   d_metaf[NN];     // {rowptr, deg, dinv, -}
__device__ int4     d_elli[NN];      // first 4 edge indices (self-padded)
__device__ float4   d_ellw[NN];      // first 4 edge weights (self slot = dinv when deg<4)
__device__ float2   d_colw[NE];      // CSR tail (slots >= 4 only)
__device__ __half   d_hbuf[(size_t)NN*HID];
__device__ __half   d_tbuf[(size_t)NN*HID];
__device__ float    d_gsum[NG*HID];
__device__ unsigned d_gmax[NG*HID];
__device__ int      d_cnt[NG];

__device__ __forceinline__ int ld_idx32(const void* p, long long j, int is64) {
    const unsigned* u = (const unsigned*)p;
    return (int)(is64 ? u[2*j] : u[j]);
}

// ---------------- index-width detection ----------------
__global__ void detect_kernel(const unsigned* __restrict__ p) {
    __shared__ unsigned red[256];
    int t = threadIdx.x;
    unsigned v = 0;
    for (int i = 2 * t + 1; i < 4096; i += 512) v |= p[i];
    red[t] = v;
    __syncthreads();
    for (int off = 128; off > 0; off >>= 1) {
        if (t < off) red[t] |= red[t + off];
        __syncthreads();
    }
    if (t == 0) g_idx64 = (red[0] == 0) ? 1 : 0;
}

__global__ void zero_kernel(int n) {
    int i = blockIdx.x * blockDim.x + threadIdx.x;
    if (i < n) d_degE[i] = 0;
    if (i < NG * HID) { d_gsum[i] = 0.f; d_gmax[i] = 0u; }
    if (i < NG) d_cnt[i] = 0;
}

__global__ void hist_kernel(const void* __restrict__ ei, int E) {
    int e = blockIdx.x * blockDim.x + threadIdx.x;
    if (e >= E) return;
    int dd = ld_idx32(ei, (long long)E + e, g_idx64);
    atomicAdd(&d_degE[dd], 1);
}

__global__ void dinv_kernel(int n) {
    int i = blockIdx.x * blockDim.x + threadIdx.x;
    if (i < n) d_dinv[i] = rsqrtf((float)d_degE[i] + 1.0f);
}

// ---------------- exclusive scan ----------------
__global__ void scanA_kernel(int n) {
    __shared__ int sm[SCAN_T];
    int b = blockIdx.x, t = threadIdx.x;
    int base = b * SCAN_B + t * SCAN_I;
    int v[SCAN_I];
    int s = 0;
#pragma unroll
    for (int j = 0; j < SCAN_I; j++) {
        v[j] = (base + j < n) ? d_degE[base + j] : 0;
        s += v[j];
    }
    sm[t] = s;
    __syncthreads();
    for (int off = 1; off < SCAN_T; off <<= 1) {
        int x = (t >= off) ? sm[t - off] : 0;
        __syncthreads();
        sm[t] += x;
        __syncthreads();
    }
    int excl = (t > 0) ? sm[t - 1] : 0;
    if (t == SCAN_T - 1) d_bsums[b] = sm[t];
    int run = excl;
#pragma unroll
    for (int j = 0; j < SCAN_I; j++) {
        if (base + j < n) d_rowptr[base + j] = run;
        run += v[j];
    }
}

__global__ void scanB_kernel(int nb) {
    __shared__ int sm[512];
    int t = threadIdx.x;
    sm[t] = (t < nb) ? d_bsums[t] : 0;
    __syncthreads();
    for (int off = 1; off < 512; off <<= 1) {
        int x = (t >= off) ? sm[t - off] : 0;
        __syncthreads();
        sm[t] += x;
        __syncthreads();
    }
    int excl = (t > 0) ? sm[t - 1] : 0;
    if (t < nb) d_bsums[t] = excl;
}

__global__ void scanC_kernel(int n) {
    int i = blockIdx.x * blockDim.x + threadIdx.x;
    if (i < n) {
        int v = d_rowptr[i] + d_bsums[i / SCAN_B];
        d_rowptr[i] = v;
        d_cursor[i] = v;
        int cnt = d_degE[i];
        float di = d_dinv[i];
        d_metaf[i] = make_float4(__int_as_float(v), __int_as_float(cnt), di, 0.f);
        d_elli[i] = make_int4(i, i, i, i);
        d_ellw[i] = make_float4(cnt == 0 ? di : 0.f, cnt == 1 ? di : 0.f,
                                cnt == 2 ? di : 0.f, cnt == 3 ? di : 0.f);
    }
}

__global__ void scatter_kernel(const void* __restrict__ ei, int E) {
    int e = blockIdx.x * blockDim.x + threadIdx.x;
    if (e >= E) return;
    int is64 = g_idx64;
    int ss = ld_idx32(ei, e, is64);
    int dd = ld_idx32(ei, (long long)E + e, is64);
    int pos = atomicAdd(&d_cursor[dd], 1);
    int j = pos - d_rowptr[dd];
    float wv = d_dinv[ss];
    if (j < 4) {
        ((int*)&d_elli[dd])[j] = ss;
        ((float*)&d_ellw[dd])[j] = wv;
    } else {
        d_colw[pos] = make_float2(__int_as_float(ss), wv);
    }
}

// ---------------- fast bf16x2 split (layer-0 GEMM) ----------------
__device__ __forceinline__ void split2(float v0, float v1, uint32_t& hi, uint32_t& lo) {
    uint32_t h;
    asm("cvt.rn.bf16x2.f32 %0, %1, %2;" : "=r"(h) : "f"(v1), "f"(v0));
    float f0 = __uint_as_float(h << 16);
    float f1 = __uint_as_float(h & 0xFFFF0000u);
    asm("cvt.rn.bf16x2.f32 %0, %1, %2;" : "=r"(lo) : "f"(v1 - f1), "f"(v0 - f0));
    hi = h;
}

// ---------------- f16x2 split (W for fused layers) ----------------
__device__ __forceinline__ void split2h(float v0, float v1, uint32_t& hi, uint32_t& lo) {
    __half2 h2 = __floats2half2_rn(v0, v1);
    float2 f = __half22float2(h2);
    __half2 l2 = __floats2half2_rn(v0 - f.x, v1 - f.y);
    hi = *(uint32_t*)&h2;
    lo = *(uint32_t*)&l2;
}

#define MMA_BF16(c, a, b0v, b1v) \
    asm volatile("mma.sync.aligned.m16n8k16.row.col.f32.bf16.bf16.f32 " \
        "{%0,%1,%2,%3}, {%4,%5,%6,%7}, {%8,%9}, {%0,%1,%2,%3};" \
        : "+f"((c)[0]), "+f"((c)[1]), "+f"((c)[2]), "+f"((c)[3]) \
        : "r"((a)[0]), "r"((a)[1]), "r"((a)[2]), "r"((a)[3]), "r"(b0v), "r"(b1v))

#define MMA_F16(c, a, b0v, b1v) \
    asm volatile("mma.sync.aligned.m16n8k16.row.col.f32.f16.f16.f32 " \
        "{%0,%1,%2,%3}, {%4,%5,%6,%7}, {%8,%9}, {%0,%1,%2,%3};" \
        : "+f"((c)[0]), "+f"((c)[1]), "+f"((c)[2]), "+f"((c)[3]) \
        : "r"((a)[0]), "r"((a)[1]), "r"((a)[2]), "r"((a)[3]), "r"(b0v), "r"(b1v))

// ---------------- layer-0 GEMM: t[N,64] = in[N,128] @ W[128,64], fp16 output ----------------
__global__ void __launch_bounds__(256, 3) gemm_mma128(const float* __restrict__ in,
                                                      const float* __restrict__ W,
                                                      __half* __restrict__ out, int n) {
    constexpr int K = 128, K2 = 64, WST = 72, NKC = 8;
    __shared__ uint32_t Wh[K2 * WST];
    __shared__ uint32_t Wl[K2 * WST];

    int tid = threadIdx.x, wid = tid >> 5, lane = tid & 31;
    int rb = blockIdx.x * 128;
    int nrows = min(128, n - rb);

    for (int i = tid; i < K2 * 64; i += 256) {
        int p = i >> 6, nn = i & 63;
        int chunk = p >> 3, m = p & 7;
        int o = (chunk << 3) + ((m < 4) ? 2 * m : 2 * (m - 4) + 1);
        uint32_t hi, lo;
        split2(W[(2 * o) * 64 + nn], W[(2 * o + 1) * 64 + nn], hi, lo);
        Wh[p * WST + nn] = hi;
        Wl[p * WST + nn] = lo;
    }
    __syncthreads();

    int qr = lane >> 2, qc = lane & 3;
    int r0 = wid * 16 + qr;
    const float* base0 = in + (size_t)(rb + min(r0, nrows - 1)) * K;
    const float* base1 = in + (size_t)(rb + min(r0 + 8, nrows - 1)) * K;

    float acc[8][4];
#pragma unroll
    for (int t = 0; t < 8; t++)
#pragma unroll
        for (int j = 0; j < 4; j++) acc[t][j] = 0.f;

    float4 pf[2][2];
    pf[0][0] = __ldg((const float4*)(base0 + 4 * qc));
    pf[0][1] = __ldg((const float4*)(base1 + 4 * qc));
    pf[1][0] = __ldg((const float4*)(base0 + 16 + 4 * qc));
    pf[1][1] = __ldg((const float4*)(base1 + 16 + 4 * qc));

#pragma unroll
    for (int kc = 0; kc < NKC; kc++) {
        float4 a0 = pf[kc & 1][0], a1 = pf[kc & 1][1];
        if (kc + 2 < NKC) {
            int cn = (kc + 2) * 16 + 4 * qc;
            pf[kc & 1][0] = __ldg((const float4*)(base0 + cn));
            pf[kc & 1][1] = __ldg((const float4*)(base1 + cn));
        }
        uint32_t ah[4], al[4];
        split2(a0.x, a0.y, ah[0], al[0]);
        split2(a1.x, a1.y, ah[1], al[1]);
        split2(a0.z, a0.w, ah[2], al[2]);
        split2(a1.z, a1.w, ah[3], al[3]);

        int bb = (kc * 8 + qc) * WST + qr;
#pragma unroll
        for (int t = 0; t < 8; t++) {
            uint32_t bh0 = Wh[bb + 8 * t];
            uint32_t bh1 = Wh[bb + 4 * WST + 8 * t];
            uint32_t bl0 = Wl[bb + 8 * t];
            uint32_t bl1 = Wl[bb + 4 * WST + 8 * t];
            MMA_BF16(acc[t], ah, bh0, bh1);
            MMA_BF16(acc[t], ah, bl0, bl1);
            MMA_BF16(acc[t], al, bh0, bh1);
        }
    }

    bool ok0 = (r0 < nrows), ok1 = (r0 + 8 < nrows);
    __half* o0 = out + (size_t)(rb + r0) * 64;
    __half* o1 = out + (size_t)(rb + r0 + 8) * 64;
#pragma unroll
    for (int t = 0; t < 8; t++) {
        int c = 8 * t + qc * 2;
        if (ok0) *(__half2*)(o0 + c) = __floats2half2_rn(acc[t][0], acc[t][1]);
        if (ok1) *(__half2*)(o1 + c) = __floats2half2_rn(acc[t][2], acc[t][3]);
    }
}

// ---------------- ELL aggregate body: 4 preloaded gathers + self/tail for deg>=4 ----------------
__device__ __forceinline__ float4 agg_body_ell(const uint2* __restrict__ t2, int c4,
                                               float di, const uint2* u, float4 ew,
                                               int start, int cnt, int selfi, float4 bb) {
    float ax = 0.f, ay = 0.f, az = 0.f, aw = 0.f;
    float2 a, b;
    a = __half22float2(*(const __half2*)&u[0].x); b = __half22float2(*(const __half2*)&u[0].y);
    ax += ew.x * a.x; ay += ew.x * a.y; az += ew.x * b.x; aw += ew.x * b.y;
    a = __half22float2(*(const __half2*)&u[1].x); b = __half22float2(*(const __half2*)&u[1].y);
    ax += ew.y * a.x; ay += ew.y * a.y; az += ew.y * b.x; aw += ew.y * b.y;
    a = __half22float2(*(const __half2*)&u[2].x); b = __half22float2(*(const __half2*)&u[2].y);
    ax += ew.z * a.x; ay += ew.z * a.y; az += ew.z * b.x; aw += ew.z * b.y;
    a = __half22float2(*(const __half2*)&u[3].x); b = __half22float2(*(const __half2*)&u[3].y);
    ax += ew.w * a.x; ay += ew.w * a.y; az += ew.w * b.x; aw += ew.w * b.y;
    if (cnt >= 4) {
        uint2 sv = __ldg(t2 + (size_t)selfi * 16 + c4);
        a = __half22float2(*(const __half2*)&sv.x); b = __half22float2(*(const __half2*)&sv.y);
        ax += di * a.x; ay += di * a.y; az += di * b.x; aw += di * b.y;
        for (int j = 4; j < cnt; j += 4) {
            int lim = cnt - 1;
            float2 c0 = __ldg(&d_colw[start + j]);
            float2 c1 = __ldg(&d_colw[start + min(j + 1, lim)]);
            float2 c2 = __ldg(&d_colw[start + min(j + 2, lim)]);
            float2 c3 = __ldg(&d_colw[start + min(j + 3, lim)]);
            float w0 = c0.y;
            float w1 = (j + 1 <= lim) ? c1.y : 0.f;
            float w2 = (j + 2 <= lim) ? c2.y : 0.f;
            float w3 = (j + 3 <= lim) ? c3.y : 0.f;
            uint2 v0 = __ldg(t2 + (size_t)__float_as_int(c0.x) * 16 + c4);
            uint2 v1 = __ldg(t2 + (size_t)__float_as_int(c1.x) * 16 + c4);
            uint2 v2 = __ldg(t2 + (size_t)__float_as_int(c2.x) * 16 + c4);
            uint2 v3 = __ldg(t2 + (size_t)__float_as_int(c3.x) * 16 + c4);
            a = __half22float2(*(const __half2*)&v0.x); b = __half22float2(*(const __half2*)&v0.y);
            ax += w0 * a.x; ay += w0 * a.y; az += w0 * b.x; aw += w0 * b.y;
            a = __half22float2(*(const __half2*)&v1.x); b = __half22float2(*(const __half2*)&v1.y);
            ax += w1 * a.x; ay += w1 * a.y; az += w1 * b.x; aw += w1 * b.y;
            a = __half22float2(*(const __half2*)&v2.x); b = __half22float2(*(const __half2*)&v2.y);
            ax += w2 * a.x; ay += w2 * a.y; az += w2 * b.x; aw += w2 * b.y;
            a = __half22float2(*(const __half2*)&v3.x); b = __half22float2(*(const __half2*)&v3.y);
            ax += w3 * a.x; ay += w3 * a.y; az += w3 * b.x; aw += w3 * b.y;
        }
    }
    return make_float4(fmaxf(di * ax + bb.x, 0.f), fmaxf(di * ay + bb.y, 0.f),
                       fmaxf(di * az + bb.z, 0.f), fmaxf(di * aw + bb.w, 0.f));
}

// ---------------- fused aggregate + GEMM64 (f16 A, f16 hi/lo W, 2-pass MMA) ----------------
__global__ void __launch_bounds__(256, 4) fused_agg_gemm(const __half* __restrict__ t,
                                                         const float* __restrict__ bias,
                                                         const float* __restrict__ W,
                                                         __half* __restrict__ out, int n) {
    constexpr int AST = 36, WST = 72, NKC = 4;
    extern __shared__ uint32_t sm[];
    uint32_t* Ast = sm;                  // [128][36] f16x2 words
    uint32_t* Wh = Ast + 128 * AST;      // [32][72]
    uint32_t* Wl = Wh + 32 * WST;

    int tid = threadIdx.x, wid = tid >> 5, lane = tid & 31;
    int rb = blockIdx.x * 128;
    int nrows = min(128, n - rb);

    for (int i = tid; i < 32 * 64; i += 256) {
        int k2 = i >> 6, nn = i & 63;
        uint32_t hi, lo;
        split2h(W[(2 * k2) * 64 + nn], W[(2 * k2 + 1) * 64 + nn], hi, lo);
        Wh[k2 * WST + nn] = hi;
        Wl[k2 * WST + nn] = lo;
    }

    // phase 1: half-warp per node, groups 2-ahead, gathers 1-ahead
    {
        int half = lane >> 4, c4 = lane & 15;
        const uint2* t2 = (const uint2*)t;
        float4 bb = __ldg((const float4*)bias + c4);
        int base = wid * 16 + half * 8;
        int ilim = nrows - 1;

        int iA = rb + min(base, ilim);
        float4 mA = __ldg(&d_metaf[iA]);
        int4   eA = __ldg(&d_elli[iA]);
        float4 wA = __ldg(&d_ellw[iA]);
        int iB = rb + min(base + 1, ilim);
        float4 mB = __ldg(&d_metaf[iB]);
        int4   eB = __ldg(&d_elli[iB]);
        float4 wB = __ldg(&d_ellw[iB]);
        uint2 u0 = __ldg(t2 + (size_t)eA.x * 16 + c4);
        uint2 u1 = __ldg(t2 + (size_t)eA.y * 16 + c4);
        uint2 u2 = __ldg(t2 + (size_t)eA.z * 16 + c4);
        uint2 u3 = __ldg(t2 + (size_t)eA.w * 16 + c4);

#pragma unroll 1
        for (int p = 0; p < 8; p++) {
            float4 mC = mB; int4 eC = eB; float4 wC = wB;
            if (p + 2 < 8) {
                int iC = rb + min(base + p + 2, ilim);
                mC = __ldg(&d_metaf[iC]);
                eC = __ldg(&d_elli[iC]);
                wC = __ldg(&d_ellw[iC]);
            }
            uint2 n0 = u0, n1 = u1, n2 = u2, n3 = u3;
            if (p + 1 < 8) {
                n0 = __ldg(t2 + (size_t)eB.x * 16 + c4);
                n1 = __ldg(t2 + (size_t)eB.y * 16 + c4);
                n2 = __ldg(t2 + (size_t)eB.z * 16 + c4);
                n3 = __ldg(t2 + (size_t)eB.w * 16 + c4);
            }
            int r = base + p;
            uint2 uu[4] = {u0, u1, u2, u3};
            float4 h = make_float4(0.f, 0.f, 0.f, 0.f);
            if (r < nrows)
                h = agg_body_ell(t2, c4, mA.z, uu, wA,
                                 __float_as_int(mA.x), __float_as_int(mA.y), rb + r, bb);
            __half2 p0 = __floats2half2_rn(h.x, h.y);
            __half2 p1 = __floats2half2_rn(h.z, h.w);
            Ast[r * AST + 2 * c4] = *(uint32_t*)&p0;
            Ast[r * AST + 2 * c4 + 1] = *(uint32_t*)&p1;
            mA = mB; eA = eB; wA = wB;
            mB = mC; eB = eC; wB = wC;
            u0 = n0; u1 = n1; u2 = n2; u3 = n3;
        }
    }
    __syncthreads();

    // phase 2: f16 MMA from smem, 2 passes (Whi, Wlo)
    int qr = lane >> 2, qc = lane & 3;
    int r0 = wid * 16 + qr;
    float acc[8][4];
#pragma unroll
    for (int t8 = 0; t8 < 8; t8++)
#pragma unroll
        for (int j = 0; j < 4; j++) acc[t8][j] = 0.f;

#pragma unroll
    for (int kc = 0; kc < NKC; kc++) {
        int ab = r0 * AST + kc * 8 + qc;
        uint32_t a4[4];
        a4[0] = Ast[ab];         a4[1] = Ast[ab + 8 * AST];
        a4[2] = Ast[ab + 4];     a4[3] = Ast[ab + 8 * AST + 4];
        int bb2 = (kc * 8 + qc) * WST + qr;
#pragma unroll
        for (int t8 = 0; t8 < 8; t8++) {
            uint32_t bh0 = Wh[bb2 + 8 * t8];
            uint32_t bh1 = Wh[bb2 + 4 * WST + 8 * t8];
            uint32_t bl0 = Wl[bb2 + 8 * t8];
            uint32_t bl1 = Wl[bb2 + 4 * WST + 8 * t8];
            MMA_F16(acc[t8], a4, bh0, bh1);
            MMA_F16(acc[t8], a4, bl0, bl1);
        }
    }

    bool ok0 = (r0 < nrows), ok1 = (r0 + 8 < nrows);
    __half* o0 = out + (size_t)(rb + r0) * 64;
    __half* o1 = out + (size_t)(rb + r0 + 8) * 64;
#pragma unroll
    for (int t8 = 0; t8 < 8; t8++) {
        int c = 8 * t8 + qc * 2;
        if (ok0) *(__half2*)(o0 + c) = __floats2half2_rn(acc[t8][0], acc[t8][1]);
        if (ok1) *(__half2*)(o1 + c) = __floats2half2_rn(acc[t8][2], acc[t8][3]);
    }
}

// ---------------- fused aggregate + pool (ELL, deep pipeline) ----------------
__global__ void __launch_bounds__(256, 4) fused_agg_pool(const __half* __restrict__ t,
                                                         const float* __restrict__ bias,
                                                         const void* __restrict__ batch, int n) {
    int tid = threadIdx.x, wid = tid >> 5, lane = tid & 31;
    int half = lane >> 4, c4 = lane & 15;
    int is64 = g_idx64;
    const uint2* t2 = (const uint2*)t;
    float4 bb = __ldg((const float4*)bias + c4);
    int base = blockIdx.x * 128 + wid * 16 + half * 8;
    if (base >= n) return;
    int ilim = n - 1;

    int curg = -1, lc = 0;
    float4 ls = make_float4(0.f, 0.f, 0.f, 0.f);
    float4 lm = make_float4(0.f, 0.f, 0.f, 0.f);

    auto flush = [&]() {
        if (curg >= 0) {
            int o = curg * HID + 4 * c4;
            atomicAdd(&d_gsum[o + 0], ls.x);
            atomicAdd(&d_gsum[o + 1], ls.y);
            atomicAdd(&d_gsum[o + 2], ls.z);
            atomicAdd(&d_gsum[o + 3], ls.w);
            atomicMax(&d_gmax[o + 0], __float_as_uint(lm.x));
            atomicMax(&d_gmax[o + 1], __float_as_uint(lm.y));
            atomicMax(&d_gmax[o + 2], __float_as_uint(lm.z));
            atomicMax(&d_gmax[o + 3], __float_as_uint(lm.w));
            if (c4 == 0) atomicAdd(&d_cnt[curg], lc);
        }
    };

    int iA = min(base, ilim);
    float4 mA = __ldg(&d_metaf[iA]);
    int4   eA = __ldg(&d_elli[iA]);
    float4 wA = __ldg(&d_ellw[iA]);
    int iB = min(base + 1, ilim);
    float4 mB = __ldg(&d_metaf[iB]);
    int4   eB = __ldg(&d_elli[iB]);
    float4 wB = __ldg(&d_ellw[iB]);
    uint2 u0 = __ldg(t2 + (size_t)eA.x * 16 + c4);
    uint2 u1 = __ldg(t2 + (size_t)eA.y * 16 + c4);
    uint2 u2 = __ldg(t2 + (size_t)eA.z * 16 + c4);
    uint2 u3 = __ldg(t2 + (size_t)eA.w * 16 + c4);

#pragma unroll 1
    for (int p = 0; p < 8; p++) {
        float4 mC = mB; int4 eC = eB; float4 wC = wB;
        if (p + 2 < 8) {
            int iC = min(base + p + 2, ilim);
            mC = __ldg(&d_metaf[iC]);
            eC = __ldg(&d_elli[iC]);
            wC = __ldg(&d_ellw[iC]);
        }
        uint2 n0 = u0, n1 = u1, n2 = u2, n3 = u3;
        if (p + 1 < 8) {
            n0 = __ldg(t2 + (size_t)eB.x * 16 + c4);
            n1 = __ldg(t2 + (size_t)eB.y * 16 + c4);
            n2 = __ldg(t2 + (size_t)eB.z * 16 + c4);
            n3 = __ldg(t2 + (size_t)eB.w * 16 + c4);
        }
        int i = base + p;
        if (i < n) {
            int g = ld_idx32(batch, i, is64);
            if (g != curg) {
                flush();
                curg = g; lc = 0;
                ls = make_float4(0.f, 0.f, 0.f, 0.f);
                lm = make_float4(0.f, 0.f, 0.f, 0.f);
            }
            uint2 uu[4] = {u0, u1, u2, u3};
            float4 h = agg_body_ell(t2, c4, mA.z, uu, wA,
                                    __float_as_int(mA.x), __float_as_int(mA.y), i, bb);
            ls.x += h.x; ls.y += h.y; ls.z += h.z; ls.w += h.w;
            lm.x = fmaxf(lm.x, h.x); lm.y = fmaxf(lm.y, h.y);
            lm.z = fmaxf(lm.z, h.z); lm.w = fmaxf(lm.w, h.w);
            lc++;
        }
        mA = mB; eA = eB; wA = wB;
        mB = mC; eB = eC; wB = wC;
        u0 = n0; u1 = n1; u2 = n2; u3 = n3;
    }
    flush();
}

// ---------------- final ----------------
__global__ void final_kernel(const float* __restrict__ Wout, const float* __restrict__ bout,
                             float* __restrict__ out) {
    __shared__ float p[2 * HID];
    int g = blockIdx.x;
    int t = threadIdx.x;  // 128
    if (t < HID) {
        float cn = fmaxf((float)d_cnt[g], 1.f);
        p[t] = d_gsum[g * HID + t] / cn;
        p[HID + t] = __uint_as_float(d_gmax[g * HID + t]);
    }
    __syncthreads();
    if (t < NC) {
        float a = bout[t];
#pragma unroll 16
        for (int k = 0; k < 2 * HID; k++) a += p[k] * Wout[k * NC + t];
        out[g * NC + t] = a;
    }
}

// ---------------- launch ----------------
extern "C" void kernel_launch(void* const* d_in, const int* in_sizes, int n_in,
                              void* d_out, int out_size) {
    const float* x    = (const float*)d_in[0];
    const void*  ei   = d_in[1];
    const void*  bat  = d_in[2];
    const float* W0   = (const float*)d_in[3];
    const float* b0   = (const float*)d_in[4];
    const float* W1   = (const float*)d_in[5];
    const float* b1   = (const float*)d_in[6];
    const float* W2   = (const float*)d_in[7];
    const float* b2   = (const float*)d_in[8];
    const float* Wout = (const float*)d_in[9];
    const float* bout = (const float*)d_in[10];
    float* out = (float*)d_out;

    int N = in_sizes[2];
    int E = in_sizes[1] / 2;

    __half *hp, *tp;
    cudaGetSymbolAddress((void**)&hp, d_hbuf);
    cudaGetSymbolAddress((void**)&tp, d_tbuf);

    int fsmem = (128 * 36 + 2 * 32 * 72) * 4;  // 36864
    cudaFuncSetAttribute(fused_agg_gemm, cudaFuncAttributeMaxDynamicSharedMemorySize, fsmem);

    int gblk = (N + 127) / 128;

    static cudaStream_t s2 = nullptr;
    static cudaEvent_t evFork = nullptr, evJoin = nullptr;
    if (s2 == nullptr) {
        cudaStreamCreateWithFlags(&s2, cudaStreamNonBlocking);
        cudaEventCreateWithFlags(&evFork, cudaEventDisableTiming);
        cudaEventCreateWithFlags(&evJoin, cudaEventDisableTiming);
    }

    // fork: CSR build on s2, layer-0 GEMM on main stream
    cudaEventRecord(evFork, 0);
    cudaStreamWaitEvent(s2, evFork, 0);

    detect_kernel<<<1, 256, 0, s2>>>((const unsigned*)ei);
    zero_kernel<<<(N + 255) / 256, 256, 0, s2>>>(N);
    hist_kernel<<<(E + 255) / 256, 256, 0, s2>>>(ei, E);
    dinv_kernel<<<(N + 255) / 256, 256, 0, s2>>>(N);
    int nb = (N + SCAN_B - 1) / SCAN_B;
    scanA_kernel<<<nb, SCAN_T, 0, s2>>>(N);
    scanB_kernel<<<1, 512, 0, s2>>>(nb);
    scanC_kernel<<<(N + 255) / 256, 256, 0, s2>>>(N);
    scatter_kernel<<<(E + 255) / 256, 256, 0, s2>>>(ei, E);

    gemm_mma128<<<gblk, 256>>>(x, W0, tp, N);

    cudaEventRecord(evJoin, s2);
    cudaStreamWaitEvent(0, evJoin, 0);

    fused_agg_gemm<<<gblk, 256, fsmem>>>(tp, b0, W1, hp, N);
    fused_agg_gemm<<<gblk, 256, fsmem>>>(hp, b1, W2, tp, N);
    fused_agg_pool<<<gblk, 256>>>(tp, b2, bat, N);
    final_kernel<<<NG, 128>>>(Wout, bout, out);
}